// round 15
// baseline (speedup 1.0000x reference)
#include <cuda_runtime.h>
#include <cuda_bf16.h>
#include <math.h>
#include <stdint.h>

#define Bb  4
#define Nn  2048
#define Dd  512
#define Hh  8
#define DHd 64

__device__ __align__(16) __nv_bfloat16 g_QhH[(size_t)Bb * Hh * Nn * DHd];
__device__ __align__(16) __nv_bfloat16 g_QhL[(size_t)Bb * Hh * Nn * DHd];
__device__ __align__(16) __nv_bfloat16 g_KhH[(size_t)Bb * Hh * Nn * DHd];
__device__ __align__(16) __nv_bfloat16 g_KhL[(size_t)Bb * Hh * Nn * DHd];
__device__ __align__(16) __nv_bfloat16 g_VhH[(size_t)Bb * Hh * Nn * DHd];
__device__ __align__(16) __nv_bfloat16 g_VhL[(size_t)Bb * Hh * Nn * DHd];
__device__ __align__(16) __nv_bfloat16 g_ctxH[(size_t)Bb * Nn * Dd];
__device__ __align__(16) __nv_bfloat16 g_ctxL[(size_t)Bb * Nn * Dd];
__device__ __align__(16) __nv_bfloat16 g_xH[(size_t)Bb * Nn * Dd];
__device__ __align__(16) __nv_bfloat16 g_xL[(size_t)Bb * Nn * Dd];
__device__ __align__(16) __nv_bfloat16 g_WH[(size_t)4 * Dd * Dd];
__device__ __align__(16) __nv_bfloat16 g_WL[(size_t)4 * Dd * Dd];

// ---------------- helpers ----------------
__device__ __forceinline__ uint32_t smem_u32(const void* p) {
    uint32_t a;
    asm("{ .reg .u64 t; cvta.to.shared.u64 t, %1; cvt.u32.u64 %0, t; }"
        : "=r"(a) : "l"(p));
    return a;
}
__device__ __forceinline__ void split2(float a, float b, uint32_t& hi, uint32_t& lo) {
    uint32_t h;
    asm("cvt.rn.bf16x2.f32 %0, %1, %2;" : "=r"(h) : "f"(b), "f"(a));
    float ra = a - __uint_as_float(h << 16);
    float rb = b - __uint_as_float(h & 0xffff0000u);
    asm("cvt.rn.bf16x2.f32 %0, %1, %2;" : "=r"(lo) : "f"(rb), "f"(ra));
    hi = h;
}
__device__ __forceinline__ void mma16816(float* c, const uint32_t* a, const uint32_t* b) {
    asm volatile("mma.sync.aligned.m16n8k16.row.col.f32.bf16.bf16.f32 "
        "{%0,%1,%2,%3}, {%4,%5,%6,%7}, {%8,%9}, {%0,%1,%2,%3};"
        : "+f"(c[0]), "+f"(c[1]), "+f"(c[2]), "+f"(c[3])
        : "r"(a[0]), "r"(a[1]), "r"(a[2]), "r"(a[3]), "r"(b[0]), "r"(b[1]));
}
__device__ __forceinline__ void ldsm4(uint32_t* r, uint32_t addr) {
    asm volatile("ldmatrix.sync.aligned.m8n8.x4.shared.b16 {%0,%1,%2,%3}, [%4];"
        : "=r"(r[0]), "=r"(r[1]), "=r"(r[2]), "=r"(r[3]) : "r"(addr));
}
__device__ __forceinline__ void ldsm4t(uint32_t* r, uint32_t addr) {
    asm volatile("ldmatrix.sync.aligned.m8n8.x4.trans.shared.b16 {%0,%1,%2,%3}, [%4];"
        : "=r"(r[0]), "=r"(r[1]), "=r"(r[2]), "=r"(r[3]) : "r"(addr));
}
#define CP16(dst, src) asm volatile("cp.async.cg.shared.global [%0], [%1], 16;" :: "r"(dst), "l"(src))
#define CP_COMMIT()    asm volatile("cp.async.commit_group;" ::: "memory")
#define CP_WAIT(n)     asm volatile("cp.async.wait_group %0;" :: "n"(n) : "memory")

#define LOG2E   1.4426950408889634f
#define M0L2E  23.083120654223415f
__device__ __forceinline__ float expm16(float x) {
    return exp2f(fmaf(x, LOG2E, -M0L2E));
}

// ---------------- Kernel 0: pre-split x and weights ----------
#define NX4 ((size_t)Bb * Nn * Dd / 4)
#define NW4 ((size_t)Dd * Dd / 4)

__global__ __launch_bounds__(256) void presplit_kernel(
    const float* __restrict__ x,  const float* __restrict__ Wq,
    const float* __restrict__ Wk, const float* __restrict__ Wv,
    const float* __restrict__ Wo)
{
    size_t idx = (size_t)blockIdx.x * 256 + threadIdx.x;
    const float* src; __nv_bfloat16 *dH, *dL; size_t off;
    if (idx < NX4) { src = x; dH = g_xH; dL = g_xL; off = idx; }
    else {
        size_t r = idx - NX4;
        int wsel = (int)(r / NW4);
        off = r - (size_t)wsel * NW4;
        src = (wsel == 0) ? Wq : (wsel == 1) ? Wk : (wsel == 2) ? Wv : Wo;
        dH = g_WH + (size_t)wsel * Dd * Dd;
        dL = g_WL + (size_t)wsel * Dd * Dd;
    }
    float4 v = *(const float4*)(src + off * 4);
    uint32_t h0, l0, h1, l1;
    split2(v.x, v.y, h0, l0);
    split2(v.z, v.w, h1, l1);
    *(uint2*)(dH + off * 4) = make_uint2(h0, h1);
    *(uint2*)(dL + off * 4) = make_uint2(l0, l1);
}

// ===========================================================================
// Projection GEMM core (R12, passing): C[128x64], 4 warps, 32 rows/warp.
// ===========================================================================
#define PSTR   72
#define PX_B   (128 * PSTR * 2)
#define PW_B   (64 * PSTR * 2)
#define PSTAGE (2 * PX_B + 2 * PW_B)
#define PROJ_SMEM (2 * PSTAGE)

__device__ __forceinline__ void proj_core_async(
    const __nv_bfloat16* __restrict__ AH, const __nv_bfloat16* __restrict__ AL,
    const __nv_bfloat16* __restrict__ WHg, const __nv_bfloat16* __restrict__ WLg,
    int m0, int n0, float acc[2][8][4], char* smc)
{
    const uint32_t smem = smem_u32(smc);
    const int t = threadIdx.x, lane = t & 31, w = t >> 5;

    auto issue = [&](int k0, int st) {
        const uint32_t sb = smem + st * PSTAGE;
        #pragma unroll
        for (int i = 0; i < 8; i++) {
            int cidx = t + i * 128;
            int r = cidx >> 3, c8 = (cidx & 7) * 8;
            uint32_t so = (uint32_t)((r * PSTR + c8) * 2);
            size_t ga = (size_t)(m0 + r) * Dd + k0 + c8;
            CP16(sb + so, AH + ga);
            CP16(sb + PX_B + so, AL + ga);
        }
        #pragma unroll
        for (int i = 0; i < 4; i++) {
            int cidx = t + i * 128;
            int r = cidx >> 3, c8 = (cidx & 7) * 8;
            uint32_t so = (uint32_t)((r * PSTR + c8) * 2);
            size_t gw = (size_t)(n0 + r) * Dd + k0 + c8;
            CP16(sb + 2 * PX_B + so, WHg + gw);
            CP16(sb + 2 * PX_B + PW_B + so, WLg + gw);
        }
        CP_COMMIT();
    };

    #pragma unroll
    for (int rs = 0; rs < 2; rs++)
        #pragma unroll
        for (int j = 0; j < 8; j++)
            acc[rs][j][0] = acc[rs][j][1] = acc[rs][j][2] = acc[rs][j][3] = 0.0f;

    issue(0, 0);
    #pragma unroll
    for (int ks = 0; ks < 8; ks++) {
        const int cur = ks & 1;
        if (ks < 7) { issue((ks + 1) * 64, cur ^ 1); CP_WAIT(1); }
        else        { CP_WAIT(0); }
        __syncthreads();

        const uint32_t XHb = smem + cur * PSTAGE;
        const uint32_t XLb = XHb + PX_B;
        const uint32_t WHb = XHb + 2 * PX_B;
        const uint32_t WLb = WHb + PW_B;

        uint32_t ah[2][4][4], al[2][4][4];
        #pragma unroll
        for (int rs = 0; rs < 2; rs++)
            #pragma unroll
            for (int c = 0; c < 4; c++) {
                uint32_t off = (uint32_t)(((32 * w + 16 * rs + (lane & 15)) * PSTR
                                           + c * 16 + (lane >> 4) * 8) * 2);
                ldsm4(ah[rs][c], XHb + off);
                ldsm4(al[rs][c], XLb + off);
            }
        #pragma unroll
        for (int j = 0; j < 8; j++) {
            uint32_t rowoff = (uint32_t)((8 * j + (lane & 7)) * (PSTR * 2));
            uint32_t koff   = (uint32_t)(((lane >> 3) * 8) * 2);
            uint32_t bh8[8], bl8[8];
            ldsm4(bh8,     WHb + rowoff + koff);
            ldsm4(bh8 + 4, WHb + rowoff + koff + 64);
            ldsm4(bl8,     WLb + rowoff + koff);
            ldsm4(bl8 + 4, WLb + rowoff + koff + 64);
            #pragma unroll
            for (int rs = 0; rs < 2; rs++)
                #pragma unroll
                for (int c = 0; c < 4; c++) {
                    mma16816(acc[rs][j], ah[rs][c], &bh8[2 * c]);
                    mma16816(acc[rs][j], ah[rs][c], &bl8[2 * c]);
                    mma16816(acc[rs][j], al[rs][c], &bh8[2 * c]);
                }
        }
        __syncthreads();
    }
}

// ---------------- Kernel 1: QKV projection + LayerNorm (Q pre-scaled) -----
__global__ __launch_bounds__(128, 2) void qkv_mma_kernel(
    const float* __restrict__ bq, const float* __restrict__ bk,
    const float* __restrict__ bv,
    const float* __restrict__ qg, const float* __restrict__ qb,
    const float* __restrict__ kg, const float* __restrict__ kb)
{
    extern __shared__ char smc[];
    const int t = threadIdx.x, lane = t & 31, w = t >> 5;
    const int g = lane >> 2, tig = lane & 3;
    const int bx = blockIdx.x, by = blockIdx.y, z = blockIdx.z;

    const float* bvec;
    __nv_bfloat16 *outH, *outL;
    const float* gamma = nullptr; const float* beta = nullptr;
    if (z == 0)      { bvec = bq; outH = g_QhH; outL = g_QhL; gamma = qg; beta = qb; }
    else if (z == 1) { bvec = bk; outH = g_KhH; outL = g_KhL; gamma = kg; beta = kb; }
    else             { bvec = bv; outH = g_VhH; outL = g_VhL; }

    const int m0 = by * 128, n0 = bx * 64;
    float acc[2][8][4];
    proj_core_async(g_xH, g_xL, g_WH + (size_t)z * Dd * Dd,
                    g_WL + (size_t)z * Dd * Dd, m0, n0, acc, smc);

    #pragma unroll
    for (int rs = 0; rs < 2; rs++)
        #pragma unroll
        for (int j = 0; j < 8; j++) {
            float2 bb = *(const float2*)(bvec + n0 + 8 * j + 2 * tig);
            acc[rs][j][0] += bb.x; acc[rs][j][1] += bb.y;
            acc[rs][j][2] += bb.x; acc[rs][j][3] += bb.y;
        }

    if (z < 2) {
        const float sc = (z == 0) ? 0.125f : 1.0f;
        #pragma unroll
        for (int rs = 0; rs < 2; rs++) {
            float s1A = 0, s2A = 0, s1B = 0, s2B = 0;
            #pragma unroll
            for (int j = 0; j < 8; j++) {
                s1A += acc[rs][j][0] + acc[rs][j][1];
                s2A += acc[rs][j][0] * acc[rs][j][0] + acc[rs][j][1] * acc[rs][j][1];
                s1B += acc[rs][j][2] + acc[rs][j][3];
                s2B += acc[rs][j][2] * acc[rs][j][2] + acc[rs][j][3] * acc[rs][j][3];
            }
            #pragma unroll
            for (int off = 1; off <= 2; off <<= 1) {
                s1A += __shfl_xor_sync(0xffffffffu, s1A, off);
                s2A += __shfl_xor_sync(0xffffffffu, s2A, off);
                s1B += __shfl_xor_sync(0xffffffffu, s1B, off);
                s2B += __shfl_xor_sync(0xffffffffu, s2B, off);
            }
            float mA = s1A * (1.0f / 64.0f), mB = s1B * (1.0f / 64.0f);
            float rA = rsqrtf(s2A * (1.0f / 64.0f) - mA * mA + 1e-6f);
            float rB = rsqrtf(s2B * (1.0f / 64.0f) - mB * mB + 1e-6f);
            #pragma unroll
            for (int j = 0; j < 8; j++) {
                int dh = 8 * j + 2 * tig;
                float2 gg = *(const float2*)(gamma + dh);
                float2 be = *(const float2*)(beta + dh);
                gg.x *= sc; gg.y *= sc; be.x *= sc; be.y *= sc;
                acc[rs][j][0] = (acc[rs][j][0] - mA) * rA * gg.x + be.x;
                acc[rs][j][1] = (acc[rs][j][1] - mA) * rA * gg.y + be.y;
                acc[rs][j][2] = (acc[rs][j][2] - mB) * rB * gg.x + be.x;
                acc[rs][j][3] = (acc[rs][j][3] - mB) * rB * gg.y + be.y;
            }
        }
    }

    #pragma unroll
    for (int rs = 0; rs < 2; rs++) {
        const int row1 = 32 * w + 16 * rs + g;
        const int m = m0 + row1, b = m >> 11, n = m & (Nn - 1);
        const size_t base = (((size_t)b * Hh + bx) * Nn + n) * DHd + 2 * tig;
        #pragma unroll
        for (int j = 0; j < 8; j++) {
            uint32_t hA, lA, hB, lB;
            split2(acc[rs][j][0], acc[rs][j][1], hA, lA);
            split2(acc[rs][j][2], acc[rs][j][3], hB, lB);
            *(uint32_t*)(outH + base + 8 * j)           = hA;
            *(uint32_t*)(outL + base + 8 * j)           = lA;
            *(uint32_t*)(outH + base + 8 * DHd + 8 * j) = hB;
            *(uint32_t*)(outL + base + 8 * DHd + 8 * j) = lB;
        }
    }
}

// ---------------- Kernel 2: flash attention (R14 base, 3 CTAs/SM try) ------
#define KVSTR 72
#define TILE_B (64 * KVSTR * 2)
#define OFF_KH 0
#define OFF_KL TILE_B
#define OFF_VH (2 * TILE_B)
#define OFF_VL (3 * TILE_B)
#define OFF_BI (4 * TILE_B)
#define BSTR   68
#define BIAS_B (64 * BSTR * 4)
#define STAGE_B (4 * TILE_B + BIAS_B)    // 54272
#define ATT_SMEM (2 * STAGE_B)           // 108544; 3 CTAs need 162816 carveout

__global__ __launch_bounds__(128, 3) void attn_mma_kernel(const float* __restrict__ bias)
{
    extern __shared__ char smc[];
    const uint32_t smem = smem_u32(smc);

    const int t = threadIdx.x, lane = t & 31, w = t >> 5;
    const int g = lane >> 2, tig = lane & 3;
    const int qt = blockIdx.x, bh = blockIdx.y;
    const int b = bh >> 3, h = bh & 7, q0 = qt * 64;

    const __nv_bfloat16* QgH = g_QhH + ((size_t)bh * Nn + q0) * DHd;
    const __nv_bfloat16* QgL = g_QhL + ((size_t)bh * Nn + q0) * DHd;
    const __nv_bfloat16* KbH = g_KhH + (size_t)bh * Nn * DHd;
    const __nv_bfloat16* KbL = g_KhL + (size_t)bh * Nn * DHd;
    const __nv_bfloat16* VbH = g_VhH + (size_t)bh * Nn * DHd;
    const __nv_bfloat16* VbL = g_VhL + (size_t)bh * Nn * DHd;
    const float* biasq = bias + ((size_t)b * Nn + q0) * Nn;

    const int row1 = 16 * w + g;

    uint32_t qh[4][4], ql[4][4];
    #pragma unroll
    for (int c = 0; c < 4; c++) {
        const int k0 = 16 * c + 2 * tig;
        const size_t rA = (size_t)row1 * DHd, rB = (size_t)(row1 + 8) * DHd;
        qh[c][0] = *(const uint32_t*)(QgH + rA + k0);
        qh[c][1] = *(const uint32_t*)(QgH + rB + k0);
        qh[c][2] = *(const uint32_t*)(QgH + rA + k0 + 8);
        qh[c][3] = *(const uint32_t*)(QgH + rB + k0 + 8);
        ql[c][0] = *(const uint32_t*)(QgL + rA + k0);
        ql[c][1] = *(const uint32_t*)(QgL + rB + k0);
        ql[c][2] = *(const uint32_t*)(QgL + rA + k0 + 8);
        ql[c][3] = *(const uint32_t*)(QgL + rB + k0 + 8);
    }

    auto issue_stage = [&](int kt, int st) {
        const size_t toff = (size_t)kt * 64 * DHd;
        const uint32_t sb = smem + st * STAGE_B;
        #pragma unroll
        for (int i = 0; i < 4; i++) {
            int cidx = t + i * 128;
            int r = cidx >> 3, c8 = (cidx & 7) * 8;
            uint32_t so = (uint32_t)((r * KVSTR + c8) * 2);
            size_t go = toff + (size_t)r * DHd + c8;
            CP16(sb + OFF_KH + so, KbH + go);
            CP16(sb + OFF_KL + so, KbL + go);
            CP16(sb + OFF_VH + so, VbH + go);
            CP16(sb + OFF_VL + so, VbL + go);
        }
        #pragma unroll
        for (int i = 0; i < 8; i++) {
            int cidx = t + i * 128;
            int r = cidx >> 4, c4 = (cidx & 15) * 4;
            CP16(sb + OFF_BI + (uint32_t)((r * BSTR + c4) * 4),
                 biasq + (size_t)r * Nn + kt * 64 + c4);
        }
        CP_COMMIT();
    };

    float o[8][4];
    #pragma unroll
    for (int j = 0; j < 8; j++)
        #pragma unroll
        for (int k = 0; k < 4; k++) o[j][k] = 0.0f;
    float lA = 0.0f, lB = 0.0f;

    issue_stage(0, 0);

    for (int kt = 0; kt < Nn / 64; kt++) {
        const int cur = kt & 1;
        if (kt + 1 < Nn / 64) { issue_stage(kt + 1, cur ^ 1); CP_WAIT(1); }
        else                  { CP_WAIT(0); }
        __syncthreads();

        const uint32_t KHb = smem + cur * STAGE_B + OFF_KH;
        const uint32_t KLb = smem + cur * STAGE_B + OFF_KL;
        const uint32_t VHb = smem + cur * STAGE_B + OFF_VH;
        const uint32_t VLb = smem + cur * STAGE_B + OFF_VL;
        const float* bs = (const float*)(smc + cur * STAGE_B + OFF_BI);

        const float* bArow = bs + row1 * BSTR + 2 * tig;
        const float* bBrow = bArow + 8 * BSTR;
        float2 vA[8], vB[8];
        #pragma unroll
        for (int j = 0; j < 8; j++) {
            vA[j] = *(const float2*)(bArow + 8 * j);
            vB[j] = *(const float2*)(bBrow + 8 * j);
        }

        float s[8][4];
        #pragma unroll
        for (int j = 0; j < 8; j++) {
            s[j][0] = s[j][1] = s[j][2] = s[j][3] = 0.0f;
            const uint32_t rowoff = (uint32_t)((8 * j + (lane & 7)) * (KVSTR * 2));
            const uint32_t koff   = (uint32_t)(((lane >> 3) * 8) * 2);
            uint32_t bhf[8], blf[8];
            ldsm4(bhf,     KHb + rowoff + koff);
            ldsm4(bhf + 4, KHb + rowoff + koff + 64);
            ldsm4(blf,     KLb + rowoff + koff);
            ldsm4(blf + 4, KLb + rowoff + koff + 64);
            #pragma unroll
            for (int c = 0; c < 4; c++) {
                mma16816(s[j], qh[c], &bhf[2 * c]);
                mma16816(s[j], qh[c], &blf[2 * c]);
                mma16816(s[j], ql[c], &bhf[2 * c]);
            }
        }

        #pragma unroll
        for (int j = 0; j < 8; j++) {
            s[j][0] = expm16(s[j][0] + vA[j].x);
            s[j][1] = expm16(s[j][1] + vA[j].y);
            s[j][2] = expm16(s[j][2] + vB[j].x);
            s[j][3] = expm16(s[j][3] + vB[j].y);
            lA += s[j][0] + s[j][1];
            lB += s[j][2] + s[j][3];
        }

        uint32_t ph[4][4], pl[4][4];
        #pragma unroll
        for (int c = 0; c < 4; c++) {
            split2(s[2*c][0],   s[2*c][1],   ph[c][0], pl[c][0]);
            split2(s[2*c][2],   s[2*c][3],   ph[c][1], pl[c][1]);
            split2(s[2*c+1][0], s[2*c+1][1], ph[c][2], pl[c][2]);
            split2(s[2*c+1][2], s[2*c+1][3], ph[c][3], pl[c][3]);
        }

        #pragma unroll
        for (int j = 0; j < 8; j++) {
            const uint32_t rowoff = (uint32_t)((((lane >> 3) * 8) + (lane & 7)) * (KVSTR * 2));
            const uint32_t coff   = (uint32_t)(8 * j * 2);
            uint32_t vhf[8], vlf[8];
            ldsm4t(vhf,     VHb + rowoff + coff);
            ldsm4t(vhf + 4, VHb + rowoff + coff + 32 * (KVSTR * 2));
            ldsm4t(vlf,     VLb + rowoff + coff);
            ldsm4t(vlf + 4, VLb + rowoff + coff + 32 * (KVSTR * 2));
            #pragma unroll
            for (int c = 0; c < 4; c++) {
                mma16816(o[j], ph[c], &vhf[2 * c]);
                mma16816(o[j], ph[c], &vlf[2 * c]);
                mma16816(o[j], pl[c], &vhf[2 * c]);
            }
        }
        __syncthreads();
    }

    lA += __shfl_xor_sync(0xffffffffu, lA, 1);
    lA += __shfl_xor_sync(0xffffffffu, lA, 2);
    lB += __shfl_xor_sync(0xffffffffu, lB, 1);
    lB += __shfl_xor_sync(0xffffffffu, lB, 2);

    const float rlA = 1.0f / lA, rlB = 1.0f / lB;
    const size_t cbase = ((size_t)b * Nn + q0 + row1) * Dd + h * DHd + 2 * tig;
    #pragma unroll
    for (int j = 0; j < 8; j++) {
        uint32_t hA, lA_, hB, lB_;
        split2(o[j][0] * rlA, o[j][1] * rlA, hA, lA_);
        split2(o[j][2] * rlB, o[j][3] * rlB, hB, lB_);
        *(uint32_t*)(g_ctxH + cbase + 8 * j)                  = hA;
        *(uint32_t*)(g_ctxL + cbase + 8 * j)                  = lA_;
        *(uint32_t*)(g_ctxH + cbase + 8 * (size_t)Dd + 8 * j) = hB;
        *(uint32_t*)(g_ctxL + cbase + 8 * (size_t)Dd + 8 * j) = lB_;
    }
}

// ---------------- Kernel 3: output projection ------------------------------
__global__ __launch_bounds__(128, 2) void oproj_mma_kernel(
    const float* __restrict__ bo, float* __restrict__ out)
{
    extern __shared__ char smc[];
    const int t = threadIdx.x, lane = t & 31, w = t >> 5;
    const int g = lane >> 2, tig = lane & 3;
    const int bx = blockIdx.x, by = blockIdx.y;

    const int m0 = by * 128, n0 = bx * 64;
    float acc[2][8][4];
    proj_core_async(g_ctxH, g_ctxL, g_WH + (size_t)3 * Dd * Dd,
                    g_WL + (size_t)3 * Dd * Dd, m0, n0, acc, smc);

    #pragma unroll
    for (int rs = 0; rs < 2; rs++) {
        const int row1 = 32 * w + 16 * rs + g;
        const int m = m0 + row1;
        float* oA = out + (size_t)m * Dd + n0 + 2 * tig;
        float* oB = oA + 8 * (size_t)Dd;
        #pragma unroll
        for (int j = 0; j < 8; j++) {
            float2 bb = *(const float2*)(bo + n0 + 8 * j + 2 * tig);
            *(float2*)(oA + 8 * j) = make_float2(acc[rs][j][0] + bb.x, acc[rs][j][1] + bb.y);
            *(float2*)(oB + 8 * j) = make_float2(acc[rs][j][2] + bb.x, acc[rs][j][3] + bb.y);
        }
    }
}

// ---------------------------------------------------------------------------
extern "C" void kernel_launch(void* const* d_in, const int* in_sizes, int n_in,
                              void* d_out, int out_size)
{
    (void)in_sizes; (void)n_in; (void)out_size;
    const float* x    = (const float*)d_in[0];
    const float* bias = (const float*)d_in[1];
    const float* Wq   = (const float*)d_in[2];
    const float* bq   = (const float*)d_in[3];
    const float* Wk   = (const float*)d_in[4];
    const float* bk   = (const float*)d_in[5];
    const float* Wv   = (const float*)d_in[6];
    const float* bv   = (const float*)d_in[7];
    const float* Wo   = (const float*)d_in[8];
    const float* bo   = (const float*)d_in[9];
    const float* qg   = (const float*)d_in[10];
    const float* qb   = (const float*)d_in[11];
    const float* kg   = (const float*)d_in[12];
    const float* kb   = (const float*)d_in[13];
    float* out = (float*)d_out;

    cudaFuncSetAttribute(qkv_mma_kernel,
                         cudaFuncAttributeMaxDynamicSharedMemorySize, PROJ_SMEM);
    cudaFuncSetAttribute(oproj_mma_kernel,
                         cudaFuncAttributeMaxDynamicSharedMemorySize, PROJ_SMEM);
    cudaFuncSetAttribute(attn_mma_kernel,
                         cudaFuncAttributeMaxDynamicSharedMemorySize, ATT_SMEM);
    cudaFuncSetAttribute(attn_mma_kernel,
                         cudaFuncAttributePreferredSharedMemoryCarveout, 100);

    presplit_kernel<<<(unsigned)((NX4 + 4 * NW4) / 256), 256>>>(x, Wq, Wk, Wv, Wo);
    qkv_mma_kernel<<<dim3(Dd / 64, (Bb * Nn) / 128, 3), 128, PROJ_SMEM>>>(
        bq, bk, bv, qg, qb, kg, kb);
    attn_mma_kernel<<<dim3(Nn / 64, Bb * Hh), 128, ATT_SMEM>>>(bias);
    oproj_mma_kernel<<<dim3(Dd / 64, (Bb * Nn) / 128), 128, PROJ_SMEM>>>(bo, out);
}

// round 16
// speedup vs baseline: 1.1608x; 1.1608x over previous
#include <cuda_runtime.h>
#include <cuda_bf16.h>
#include <math.h>
#include <stdint.h>

#define Bb  4
#define Nn  2048
#define Dd  512
#define Hh  8
#define DHd 64

__device__ __align__(16) __nv_bfloat16 g_QhH[(size_t)Bb * Hh * Nn * DHd];
__device__ __align__(16) __nv_bfloat16 g_QhL[(size_t)Bb * Hh * Nn * DHd];
__device__ __align__(16) __nv_bfloat16 g_KhH[(size_t)Bb * Hh * Nn * DHd];
__device__ __align__(16) __nv_bfloat16 g_KhL[(size_t)Bb * Hh * Nn * DHd];
__device__ __align__(16) __nv_bfloat16 g_VhH[(size_t)Bb * Hh * Nn * DHd];
__device__ __align__(16) __nv_bfloat16 g_VhL[(size_t)Bb * Hh * Nn * DHd];
__device__ __align__(16) __nv_bfloat16 g_ctxH[(size_t)Bb * Nn * Dd];
__device__ __align__(16) __nv_bfloat16 g_ctxL[(size_t)Bb * Nn * Dd];
__device__ __align__(16) __nv_bfloat16 g_xH[(size_t)Bb * Nn * Dd];
__device__ __align__(16) __nv_bfloat16 g_xL[(size_t)Bb * Nn * Dd];
__device__ __align__(16) __nv_bfloat16 g_WH[(size_t)4 * Dd * Dd];
__device__ __align__(16) __nv_bfloat16 g_WL[(size_t)4 * Dd * Dd];

// ---------------- helpers ----------------
__device__ __forceinline__ uint32_t smem_u32(const void* p) {
    uint32_t a;
    asm("{ .reg .u64 t; cvta.to.shared.u64 t, %1; cvt.u32.u64 %0, t; }"
        : "=r"(a) : "l"(p));
    return a;
}
__device__ __forceinline__ void split2(float a, float b, uint32_t& hi, uint32_t& lo) {
    uint32_t h;
    asm("cvt.rn.bf16x2.f32 %0, %1, %2;" : "=r"(h) : "f"(b), "f"(a));
    float ra = a - __uint_as_float(h << 16);
    float rb = b - __uint_as_float(h & 0xffff0000u);
    asm("cvt.rn.bf16x2.f32 %0, %1, %2;" : "=r"(lo) : "f"(rb), "f"(ra));
    hi = h;
}
__device__ __forceinline__ void mma16816(float* c, const uint32_t* a, const uint32_t* b) {
    asm volatile("mma.sync.aligned.m16n8k16.row.col.f32.bf16.bf16.f32 "
        "{%0,%1,%2,%3}, {%4,%5,%6,%7}, {%8,%9}, {%0,%1,%2,%3};"
        : "+f"(c[0]), "+f"(c[1]), "+f"(c[2]), "+f"(c[3])
        : "r"(a[0]), "r"(a[1]), "r"(a[2]), "r"(a[3]), "r"(b[0]), "r"(b[1]));
}
__device__ __forceinline__ void ldsm4(uint32_t* r, uint32_t addr) {
    asm volatile("ldmatrix.sync.aligned.m8n8.x4.shared.b16 {%0,%1,%2,%3}, [%4];"
        : "=r"(r[0]), "=r"(r[1]), "=r"(r[2]), "=r"(r[3]) : "r"(addr));
}
__device__ __forceinline__ void ldsm4t(uint32_t* r, uint32_t addr) {
    asm volatile("ldmatrix.sync.aligned.m8n8.x4.trans.shared.b16 {%0,%1,%2,%3}, [%4];"
        : "=r"(r[0]), "=r"(r[1]), "=r"(r[2]), "=r"(r[3]) : "r"(addr));
}
#define CP16(dst, src) asm volatile("cp.async.cg.shared.global [%0], [%1], 16;" :: "r"(dst), "l"(src))
#define CP_COMMIT()    asm volatile("cp.async.commit_group;" ::: "memory")
#define CP_WAIT(n)     asm volatile("cp.async.wait_group %0;" :: "n"(n) : "memory")

#define LOG2E   1.4426950408889634f
#define M0L2E  23.083120654223415f
__device__ __forceinline__ float expm16(float x) {
    return exp2f(fmaf(x, LOG2E, -M0L2E));
}

// ---------------- Kernel 0: pre-split x and weights ----------
#define NX4 ((size_t)Bb * Nn * Dd / 4)
#define NW4 ((size_t)Dd * Dd / 4)

__global__ __launch_bounds__(256) void presplit_kernel(
    const float* __restrict__ x,  const float* __restrict__ Wq,
    const float* __restrict__ Wk, const float* __restrict__ Wv,
    const float* __restrict__ Wo)
{
    size_t idx = (size_t)blockIdx.x * 256 + threadIdx.x;
    const float* src; __nv_bfloat16 *dH, *dL; size_t off;
    if (idx < NX4) { src = x; dH = g_xH; dL = g_xL; off = idx; }
    else {
        size_t r = idx - NX4;
        int wsel = (int)(r / NW4);
        off = r - (size_t)wsel * NW4;
        src = (wsel == 0) ? Wq : (wsel == 1) ? Wk : (wsel == 2) ? Wv : Wo;
        dH = g_WH + (size_t)wsel * Dd * Dd;
        dL = g_WL + (size_t)wsel * Dd * Dd;
    }
    float4 v = *(const float4*)(src + off * 4);
    uint32_t h0, l0, h1, l1;
    split2(v.x, v.y, h0, l0);
    split2(v.z, v.w, h1, l1);
    *(uint2*)(dH + off * 4) = make_uint2(h0, h1);
    *(uint2*)(dL + off * 4) = make_uint2(l0, l1);
}

// ===========================================================================
// Projection GEMM core (R10 config): C[64x64], 4 warps, 16 rows/warp.
// regs ~154 fits the (128,3) cap; carveout=100 enables 3 CTAs/SM.
// ===========================================================================
#define PSTR   72
#define PX_B   (64 * PSTR * 2)                 // 9216
#define PW_B   (64 * PSTR * 2)                 // 9216
#define PSTAGE (2 * PX_B + 2 * PW_B)           // 36864
#define PROJ_SMEM (2 * PSTAGE)                 // 73728; 3 CTAs = 221184

__device__ __forceinline__ void proj_core_async(
    const __nv_bfloat16* __restrict__ AH, const __nv_bfloat16* __restrict__ AL,
    const __nv_bfloat16* __restrict__ WHg, const __nv_bfloat16* __restrict__ WLg,
    int m0, int n0, float acc[8][4], char* smc)
{
    const uint32_t smem = smem_u32(smc);
    const int t = threadIdx.x, lane = t & 31, w = t >> 5;

    auto issue = [&](int k0, int st) {
        const uint32_t sb = smem + st * PSTAGE;
        #pragma unroll
        for (int i = 0; i < 4; i++) {
            int cidx = t + i * 128;               // 0..511 (16B chunks)
            int r = cidx >> 3, c8 = (cidx & 7) * 8;
            uint32_t so = (uint32_t)((r * PSTR + c8) * 2);
            size_t ga = (size_t)(m0 + r) * Dd + k0 + c8;
            size_t gw = (size_t)(n0 + r) * Dd + k0 + c8;
            CP16(sb + so, AH + ga);
            CP16(sb + PX_B + so, AL + ga);
            CP16(sb + 2 * PX_B + so, WHg + gw);
            CP16(sb + 2 * PX_B + PW_B + so, WLg + gw);
        }
        CP_COMMIT();
    };

    #pragma unroll
    for (int j = 0; j < 8; j++)
        acc[j][0] = acc[j][1] = acc[j][2] = acc[j][3] = 0.0f;

    issue(0, 0);
    #pragma unroll
    for (int ks = 0; ks < 8; ks++) {
        const int cur = ks & 1;
        if (ks < 7) { issue((ks + 1) * 64, cur ^ 1); CP_WAIT(1); }
        else        { CP_WAIT(0); }
        __syncthreads();

        const uint32_t XHb = smem + cur * PSTAGE;
        const uint32_t XLb = XHb + PX_B;
        const uint32_t WHb = XHb + 2 * PX_B;
        const uint32_t WLb = WHb + PW_B;

        uint32_t ah[4][4], al[4][4];
        #pragma unroll
        for (int c = 0; c < 4; c++) {
            uint32_t off = (uint32_t)(((16 * w + (lane & 15)) * PSTR
                                       + c * 16 + (lane >> 4) * 8) * 2);
            ldsm4(ah[c], XHb + off);
            ldsm4(al[c], XLb + off);
        }
        #pragma unroll
        for (int j = 0; j < 8; j++) {
            uint32_t rowoff = (uint32_t)((8 * j + (lane & 7)) * (PSTR * 2));
            uint32_t koff   = (uint32_t)(((lane >> 3) * 8) * 2);
            uint32_t bh8[8], bl8[8];
            ldsm4(bh8,     WHb + rowoff + koff);
            ldsm4(bh8 + 4, WHb + rowoff + koff + 64);
            ldsm4(bl8,     WLb + rowoff + koff);
            ldsm4(bl8 + 4, WLb + rowoff + koff + 64);
            #pragma unroll
            for (int c = 0; c < 4; c++) {
                mma16816(acc[j], ah[c], &bh8[2 * c]);
                mma16816(acc[j], ah[c], &bl8[2 * c]);
                mma16816(acc[j], al[c], &bh8[2 * c]);
            }
        }
        __syncthreads();
    }
}

// ---------------- Kernel 1: QKV projection + LayerNorm (Q pre-scaled) -----
__global__ __launch_bounds__(128, 3) void qkv_mma_kernel(
    const float* __restrict__ bq, const float* __restrict__ bk,
    const float* __restrict__ bv,
    const float* __restrict__ qg, const float* __restrict__ qb,
    const float* __restrict__ kg, const float* __restrict__ kb)
{
    extern __shared__ char smc[];
    const int t = threadIdx.x, lane = t & 31, w = t >> 5;
    const int g = lane >> 2, tig = lane & 3;
    const int bx = blockIdx.x, by = blockIdx.y, z = blockIdx.z;

    const float* bvec;
    __nv_bfloat16 *outH, *outL;
    const float* gamma = nullptr; const float* beta = nullptr;
    if (z == 0)      { bvec = bq; outH = g_QhH; outL = g_QhL; gamma = qg; beta = qb; }
    else if (z == 1) { bvec = bk; outH = g_KhH; outL = g_KhL; gamma = kg; beta = kb; }
    else             { bvec = bv; outH = g_VhH; outL = g_VhL; }

    const int m0 = by * 64, n0 = bx * 64;
    float acc[8][4];
    proj_core_async(g_xH, g_xL, g_WH + (size_t)z * Dd * Dd,
                    g_WL + (size_t)z * Dd * Dd, m0, n0, acc, smc);

    #pragma unroll
    for (int j = 0; j < 8; j++) {
        float2 bb = *(const float2*)(bvec + n0 + 8 * j + 2 * tig);
        acc[j][0] += bb.x; acc[j][1] += bb.y;
        acc[j][2] += bb.x; acc[j][3] += bb.y;
    }

    if (z < 2) {
        const float sc = (z == 0) ? 0.125f : 1.0f;
        float s1A = 0, s2A = 0, s1B = 0, s2B = 0;
        #pragma unroll
        for (int j = 0; j < 8; j++) {
            s1A += acc[j][0] + acc[j][1];
            s2A += acc[j][0] * acc[j][0] + acc[j][1] * acc[j][1];
            s1B += acc[j][2] + acc[j][3];
            s2B += acc[j][2] * acc[j][2] + acc[j][3] * acc[j][3];
        }
        #pragma unroll
        for (int off = 1; off <= 2; off <<= 1) {
            s1A += __shfl_xor_sync(0xffffffffu, s1A, off);
            s2A += __shfl_xor_sync(0xffffffffu, s2A, off);
            s1B += __shfl_xor_sync(0xffffffffu, s1B, off);
            s2B += __shfl_xor_sync(0xffffffffu, s2B, off);
        }
        float mA = s1A * (1.0f / 64.0f), mB = s1B * (1.0f / 64.0f);
        float rA = rsqrtf(s2A * (1.0f / 64.0f) - mA * mA + 1e-6f);
        float rB = rsqrtf(s2B * (1.0f / 64.0f) - mB * mB + 1e-6f);
        #pragma unroll
        for (int j = 0; j < 8; j++) {
            int dh = 8 * j + 2 * tig;
            float2 gg = *(const float2*)(gamma + dh);
            float2 be = *(const float2*)(beta + dh);
            gg.x *= sc; gg.y *= sc; be.x *= sc; be.y *= sc;
            acc[j][0] = (acc[j][0] - mA) * rA * gg.x + be.x;
            acc[j][1] = (acc[j][1] - mA) * rA * gg.y + be.y;
            acc[j][2] = (acc[j][2] - mB) * rB * gg.x + be.x;
            acc[j][3] = (acc[j][3] - mB) * rB * gg.y + be.y;
        }
    }

    const int row1 = 16 * w + g;
    const int m = m0 + row1, b = m >> 11, n = m & (Nn - 1);
    const size_t base = (((size_t)b * Hh + bx) * Nn + n) * DHd + 2 * tig;
    #pragma unroll
    for (int j = 0; j < 8; j++) {
        uint32_t hA, lA, hB, lB;
        split2(acc[j][0], acc[j][1], hA, lA);
        split2(acc[j][2], acc[j][3], hB, lB);
        *(uint32_t*)(outH + base + 8 * j)           = hA;
        *(uint32_t*)(outL + base + 8 * j)           = lA;
        *(uint32_t*)(outH + base + 8 * DHd + 8 * j) = hB;
        *(uint32_t*)(outL + base + 8 * DHd + 8 * j) = lB;
    }
}

// ---------------- Kernel 2: flash attention (R14, best known) --------------
#define KVSTR 72
#define TILE_B (64 * KVSTR * 2)
#define OFF_KH 0
#define OFF_KL TILE_B
#define OFF_VH (2 * TILE_B)
#define OFF_VL (3 * TILE_B)
#define OFF_BI (4 * TILE_B)
#define BSTR   68
#define BIAS_B (64 * BSTR * 4)
#define STAGE_B (4 * TILE_B + BIAS_B)
#define ATT_SMEM (2 * STAGE_B)

__global__ __launch_bounds__(128, 2) void attn_mma_kernel(const float* __restrict__ bias)
{
    extern __shared__ char smc[];
    const uint32_t smem = smem_u32(smc);

    const int t = threadIdx.x, lane = t & 31, w = t >> 5;
    const int g = lane >> 2, tig = lane & 3;
    const int qt = blockIdx.x, bh = blockIdx.y;
    const int b = bh >> 3, h = bh & 7, q0 = qt * 64;

    const __nv_bfloat16* QgH = g_QhH + ((size_t)bh * Nn + q0) * DHd;
    const __nv_bfloat16* QgL = g_QhL + ((size_t)bh * Nn + q0) * DHd;
    const __nv_bfloat16* KbH = g_KhH + (size_t)bh * Nn * DHd;
    const __nv_bfloat16* KbL = g_KhL + (size_t)bh * Nn * DHd;
    const __nv_bfloat16* VbH = g_VhH + (size_t)bh * Nn * DHd;
    const __nv_bfloat16* VbL = g_VhL + (size_t)bh * Nn * DHd;
    const float* biasq = bias + ((size_t)b * Nn + q0) * Nn;

    const int row1 = 16 * w + g;

    uint32_t qh[4][4], ql[4][4];
    #pragma unroll
    for (int c = 0; c < 4; c++) {
        const int k0 = 16 * c + 2 * tig;
        const size_t rA = (size_t)row1 * DHd, rB = (size_t)(row1 + 8) * DHd;
        qh[c][0] = *(const uint32_t*)(QgH + rA + k0);
        qh[c][1] = *(const uint32_t*)(QgH + rB + k0);
        qh[c][2] = *(const uint32_t*)(QgH + rA + k0 + 8);
        qh[c][3] = *(const uint32_t*)(QgH + rB + k0 + 8);
        ql[c][0] = *(const uint32_t*)(QgL + rA + k0);
        ql[c][1] = *(const uint32_t*)(QgL + rB + k0);
        ql[c][2] = *(const uint32_t*)(QgL + rA + k0 + 8);
        ql[c][3] = *(const uint32_t*)(QgL + rB + k0 + 8);
    }

    auto issue_stage = [&](int kt, int st) {
        const size_t toff = (size_t)kt * 64 * DHd;
        const uint32_t sb = smem + st * STAGE_B;
        #pragma unroll
        for (int i = 0; i < 4; i++) {
            int cidx = t + i * 128;
            int r = cidx >> 3, c8 = (cidx & 7) * 8;
            uint32_t so = (uint32_t)((r * KVSTR + c8) * 2);
            size_t go = toff + (size_t)r * DHd + c8;
            CP16(sb + OFF_KH + so, KbH + go);
            CP16(sb + OFF_KL + so, KbL + go);
            CP16(sb + OFF_VH + so, VbH + go);
            CP16(sb + OFF_VL + so, VbL + go);
        }
        #pragma unroll
        for (int i = 0; i < 8; i++) {
            int cidx = t + i * 128;
            int r = cidx >> 4, c4 = (cidx & 15) * 4;
            CP16(sb + OFF_BI + (uint32_t)((r * BSTR + c4) * 4),
                 biasq + (size_t)r * Nn + kt * 64 + c4);
        }
        CP_COMMIT();
    };

    float o[8][4];
    #pragma unroll
    for (int j = 0; j < 8; j++)
        #pragma unroll
        for (int k = 0; k < 4; k++) o[j][k] = 0.0f;
    float lA = 0.0f, lB = 0.0f;

    issue_stage(0, 0);

    for (int kt = 0; kt < Nn / 64; kt++) {
        const int cur = kt & 1;
        if (kt + 1 < Nn / 64) { issue_stage(kt + 1, cur ^ 1); CP_WAIT(1); }
        else                  { CP_WAIT(0); }
        __syncthreads();

        const uint32_t KHb = smem + cur * STAGE_B + OFF_KH;
        const uint32_t KLb = smem + cur * STAGE_B + OFF_KL;
        const uint32_t VHb = smem + cur * STAGE_B + OFF_VH;
        const uint32_t VLb = smem + cur * STAGE_B + OFF_VL;
        const float* bs = (const float*)(smc + cur * STAGE_B + OFF_BI);

        const float* bArow = bs + row1 * BSTR + 2 * tig;
        const float* bBrow = bArow + 8 * BSTR;
        float2 vA[8], vB[8];
        #pragma unroll
        for (int j = 0; j < 8; j++) {
            vA[j] = *(const float2*)(bArow + 8 * j);
            vB[j] = *(const float2*)(bBrow + 8 * j);
        }

        float s[8][4];
        #pragma unroll
        for (int j = 0; j < 8; j++) {
            s[j][0] = s[j][1] = s[j][2] = s[j][3] = 0.0f;
            const uint32_t rowoff = (uint32_t)((8 * j + (lane & 7)) * (KVSTR * 2));
            const uint32_t koff   = (uint32_t)(((lane >> 3) * 8) * 2);
            uint32_t bhf[8], blf[8];
            ldsm4(bhf,     KHb + rowoff + koff);
            ldsm4(bhf + 4, KHb + rowoff + koff + 64);
            ldsm4(blf,     KLb + rowoff + koff);
            ldsm4(blf + 4, KLb + rowoff + koff + 64);
            #pragma unroll
            for (int c = 0; c < 4; c++) {
                mma16816(s[j], qh[c], &bhf[2 * c]);
                mma16816(s[j], qh[c], &blf[2 * c]);
                mma16816(s[j], ql[c], &bhf[2 * c]);
            }
        }

        #pragma unroll
        for (int j = 0; j < 8; j++) {
            s[j][0] = expm16(s[j][0] + vA[j].x);
            s[j][1] = expm16(s[j][1] + vA[j].y);
            s[j][2] = expm16(s[j][2] + vB[j].x);
            s[j][3] = expm16(s[j][3] + vB[j].y);
            lA += s[j][0] + s[j][1];
            lB += s[j][2] + s[j][3];
        }

        uint32_t ph[4][4], pl[4][4];
        #pragma unroll
        for (int c = 0; c < 4; c++) {
            split2(s[2*c][0],   s[2*c][1],   ph[c][0], pl[c][0]);
            split2(s[2*c][2],   s[2*c][3],   ph[c][1], pl[c][1]);
            split2(s[2*c+1][0], s[2*c+1][1], ph[c][2], pl[c][2]);
            split2(s[2*c+1][2], s[2*c+1][3], ph[c][3], pl[c][3]);
        }

        #pragma unroll
        for (int j = 0; j < 8; j++) {
            const uint32_t rowoff = (uint32_t)((((lane >> 3) * 8) + (lane & 7)) * (KVSTR * 2));
            const uint32_t coff   = (uint32_t)(8 * j * 2);
            uint32_t vhf[8], vlf[8];
            ldsm4t(vhf,     VHb + rowoff + coff);
            ldsm4t(vhf + 4, VHb + rowoff + coff + 32 * (KVSTR * 2));
            ldsm4t(vlf,     VLb + rowoff + coff);
            ldsm4t(vlf + 4, VLb + rowoff + coff + 32 * (KVSTR * 2));
            #pragma unroll
            for (int c = 0; c < 4; c++) {
                mma16816(o[j], ph[c], &vhf[2 * c]);
                mma16816(o[j], ph[c], &vlf[2 * c]);
                mma16816(o[j], pl[c], &vhf[2 * c]);
            }
        }
        __syncthreads();
    }

    lA += __shfl_xor_sync(0xffffffffu, lA, 1);
    lA += __shfl_xor_sync(0xffffffffu, lA, 2);
    lB += __shfl_xor_sync(0xffffffffu, lB, 1);
    lB += __shfl_xor_sync(0xffffffffu, lB, 2);

    const float rlA = 1.0f / lA, rlB = 1.0f / lB;
    const size_t cbase = ((size_t)b * Nn + q0 + row1) * Dd + h * DHd + 2 * tig;
    #pragma unroll
    for (int j = 0; j < 8; j++) {
        uint32_t hA, lA_, hB, lB_;
        split2(o[j][0] * rlA, o[j][1] * rlA, hA, lA_);
        split2(o[j][2] * rlB, o[j][3] * rlB, hB, lB_);
        *(uint32_t*)(g_ctxH + cbase + 8 * j)                  = hA;
        *(uint32_t*)(g_ctxL + cbase + 8 * j)                  = lA_;
        *(uint32_t*)(g_ctxH + cbase + 8 * (size_t)Dd + 8 * j) = hB;
        *(uint32_t*)(g_ctxL + cbase + 8 * (size_t)Dd + 8 * j) = lB_;
    }
}

// ---------------- Kernel 3: output projection ------------------------------
__global__ __launch_bounds__(128, 3) void oproj_mma_kernel(
    const float* __restrict__ bo, float* __restrict__ out)
{
    extern __shared__ char smc[];
    const int t = threadIdx.x, lane = t & 31, w = t >> 5;
    const int g = lane >> 2, tig = lane & 3;
    const int bx = blockIdx.x, by = blockIdx.y;

    const int m0 = by * 64, n0 = bx * 64;
    float acc[8][4];
    proj_core_async(g_ctxH, g_ctxL, g_WH + (size_t)3 * Dd * Dd,
                    g_WL + (size_t)3 * Dd * Dd, m0, n0, acc, smc);

    const int row1 = 16 * w + g;
    const int m = m0 + row1;
    float* oA = out + (size_t)m * Dd + n0 + 2 * tig;
    float* oB = oA + 8 * (size_t)Dd;
    #pragma unroll
    for (int j = 0; j < 8; j++) {
        float2 bb = *(const float2*)(bo + n0 + 8 * j + 2 * tig);
        *(float2*)(oA + 8 * j) = make_float2(acc[j][0] + bb.x, acc[j][1] + bb.y);
        *(float2*)(oB + 8 * j) = make_float2(acc[j][2] + bb.x, acc[j][3] + bb.y);
    }
}

// ---------------------------------------------------------------------------
extern "C" void kernel_launch(void* const* d_in, const int* in_sizes, int n_in,
                              void* d_out, int out_size)
{
    (void)in_sizes; (void)n_in; (void)out_size;
    const float* x    = (const float*)d_in[0];
    const float* bias = (const float*)d_in[1];
    const float* Wq   = (const float*)d_in[2];
    const float* bq   = (const float*)d_in[3];
    const float* Wk   = (const float*)d_in[4];
    const float* bk   = (const float*)d_in[5];
    const float* Wv   = (const float*)d_in[6];
    const float* bv   = (const float*)d_in[7];
    const float* Wo   = (const float*)d_in[8];
    const float* bo   = (const float*)d_in[9];
    const float* qg   = (const float*)d_in[10];
    const float* qb   = (const float*)d_in[11];
    const float* kg   = (const float*)d_in[12];
    const float* kb   = (const float*)d_in[13];
    float* out = (float*)d_out;

    cudaFuncSetAttribute(qkv_mma_kernel,
                         cudaFuncAttributeMaxDynamicSharedMemorySize, PROJ_SMEM);
    cudaFuncSetAttribute(qkv_mma_kernel,
                         cudaFuncAttributePreferredSharedMemoryCarveout, 100);
    cudaFuncSetAttribute(oproj_mma_kernel,
                         cudaFuncAttributeMaxDynamicSharedMemorySize, PROJ_SMEM);
    cudaFuncSetAttribute(oproj_mma_kernel,
                         cudaFuncAttributePreferredSharedMemoryCarveout, 100);
    cudaFuncSetAttribute(attn_mma_kernel,
                         cudaFuncAttributeMaxDynamicSharedMemorySize, ATT_SMEM);

    presplit_kernel<<<(unsigned)((NX4 + 4 * NW4) / 256), 256>>>(x, Wq, Wk, Wv, Wo);
    qkv_mma_kernel<<<dim3(Dd / 64, (Bb * Nn) / 64, 3), 128, PROJ_SMEM>>>(
        bq, bk, bv, qg, qb, kg, kb);
    attn_mma_kernel<<<dim3(Nn / 64, Bb * Hh), 128, ATT_SMEM>>>(bias);
    oproj_mma_kernel<<<dim3(Dd / 64, (Bb * Nn) / 64), 128, PROJ_SMEM>>>(bo, out);
}

// round 17
// speedup vs baseline: 1.1731x; 1.0106x over previous
#include <cuda_runtime.h>
#include <cuda_bf16.h>
#include <math.h>
#include <stdint.h>

#define Bb  4
#define Nn  2048
#define Dd  512
#define Hh  8
#define DHd 64

__device__ __align__(16) __nv_bfloat16 g_QhH[(size_t)Bb * Hh * Nn * DHd];
__device__ __align__(16) __nv_bfloat16 g_QhL[(size_t)Bb * Hh * Nn * DHd];
__device__ __align__(16) __nv_bfloat16 g_KhH[(size_t)Bb * Hh * Nn * DHd];
__device__ __align__(16) __nv_bfloat16 g_KhL[(size_t)Bb * Hh * Nn * DHd];
__device__ __align__(16) __nv_bfloat16 g_VhH[(size_t)Bb * Hh * Nn * DHd];
__device__ __align__(16) __nv_bfloat16 g_VhL[(size_t)Bb * Hh * Nn * DHd];
__device__ __align__(16) __nv_bfloat16 g_ctxH[(size_t)Bb * Nn * Dd];
__device__ __align__(16) __nv_bfloat16 g_ctxL[(size_t)Bb * Nn * Dd];
__device__ __align__(16) __nv_bfloat16 g_xH[(size_t)Bb * Nn * Dd];
__device__ __align__(16) __nv_bfloat16 g_xL[(size_t)Bb * Nn * Dd];
__device__ __align__(16) __nv_bfloat16 g_WH[(size_t)4 * Dd * Dd];
__device__ __align__(16) __nv_bfloat16 g_WL[(size_t)4 * Dd * Dd];

// ---------------- helpers ----------------
__device__ __forceinline__ uint32_t smem_u32(const void* p) {
    uint32_t a;
    asm("{ .reg .u64 t; cvta.to.shared.u64 t, %1; cvt.u32.u64 %0, t; }"
        : "=r"(a) : "l"(p));
    return a;
}
__device__ __forceinline__ void split2(float a, float b, uint32_t& hi, uint32_t& lo) {
    uint32_t h;
    asm("cvt.rn.bf16x2.f32 %0, %1, %2;" : "=r"(h) : "f"(b), "f"(a));
    float ra = a - __uint_as_float(h << 16);
    float rb = b - __uint_as_float(h & 0xffff0000u);
    asm("cvt.rn.bf16x2.f32 %0, %1, %2;" : "=r"(lo) : "f"(rb), "f"(ra));
    hi = h;
}
__device__ __forceinline__ void mma16816(float* c, const uint32_t* a, const uint32_t* b) {
    asm volatile("mma.sync.aligned.m16n8k16.row.col.f32.bf16.bf16.f32 "
        "{%0,%1,%2,%3}, {%4,%5,%6,%7}, {%8,%9}, {%0,%1,%2,%3};"
        : "+f"(c[0]), "+f"(c[1]), "+f"(c[2]), "+f"(c[3])
        : "r"(a[0]), "r"(a[1]), "r"(a[2]), "r"(a[3]), "r"(b[0]), "r"(b[1]));
}
__device__ __forceinline__ void ldsm4(uint32_t* r, uint32_t addr) {
    asm volatile("ldmatrix.sync.aligned.m8n8.x4.shared.b16 {%0,%1,%2,%3}, [%4];"
        : "=r"(r[0]), "=r"(r[1]), "=r"(r[2]), "=r"(r[3]) : "r"(addr));
}
__device__ __forceinline__ void ldsm4t(uint32_t* r, uint32_t addr) {
    asm volatile("ldmatrix.sync.aligned.m8n8.x4.trans.shared.b16 {%0,%1,%2,%3}, [%4];"
        : "=r"(r[0]), "=r"(r[1]), "=r"(r[2]), "=r"(r[3]) : "r"(addr));
}
#define CP16(dst, src) asm volatile("cp.async.cg.shared.global [%0], [%1], 16;" :: "r"(dst), "l"(src))
#define CP_COMMIT()    asm volatile("cp.async.commit_group;" ::: "memory")
#define CP_WAIT(n)     asm volatile("cp.async.wait_group %0;" :: "n"(n) : "memory")

#define LOG2E   1.4426950408889634f
#define M0L2E  23.083120654223415f
__device__ __forceinline__ float expm16(float x) {
    return exp2f(fmaf(x, LOG2E, -M0L2E));
}

// ---------------- Kernel 0: pre-split x and weights ----------
#define NX4 ((size_t)Bb * Nn * Dd / 4)
#define NW4 ((size_t)Dd * Dd / 4)

__global__ __launch_bounds__(256) void presplit_kernel(
    const float* __restrict__ x,  const float* __restrict__ Wq,
    const float* __restrict__ Wk, const float* __restrict__ Wv,
    const float* __restrict__ Wo)
{
    size_t idx = (size_t)blockIdx.x * 256 + threadIdx.x;
    const float* src; __nv_bfloat16 *dH, *dL; size_t off;
    if (idx < NX4) { src = x; dH = g_xH; dL = g_xL; off = idx; }
    else {
        size_t r = idx - NX4;
        int wsel = (int)(r / NW4);
        off = r - (size_t)wsel * NW4;
        src = (wsel == 0) ? Wq : (wsel == 1) ? Wk : (wsel == 2) ? Wv : Wo;
        dH = g_WH + (size_t)wsel * Dd * Dd;
        dL = g_WL + (size_t)wsel * Dd * Dd;
    }
    float4 v = *(const float4*)(src + off * 4);
    uint32_t h0, l0, h1, l1;
    split2(v.x, v.y, h0, l0);
    split2(v.z, v.w, h1, l1);
    *(uint2*)(dH + off * 4) = make_uint2(h0, h1);
    *(uint2*)(dL + off * 4) = make_uint2(l0, l1);
}

// ===========================================================================
// Projection core A (R12): C[128x64], 4 warps, 32 rows/warp — used by qkv.
// ===========================================================================
#define PSTR    72
#define PAX_B   (128 * PSTR * 2)
#define PAW_B   (64 * PSTR * 2)
#define PASTAGE (2 * PAX_B + 2 * PAW_B)
#define PROJA_SMEM (2 * PASTAGE)

__device__ __forceinline__ void proj_core_A(
    const __nv_bfloat16* __restrict__ AH, const __nv_bfloat16* __restrict__ AL,
    const __nv_bfloat16* __restrict__ WHg, const __nv_bfloat16* __restrict__ WLg,
    int m0, int n0, float acc[2][8][4], char* smc)
{
    const uint32_t smem = smem_u32(smc);
    const int t = threadIdx.x, lane = t & 31, w = t >> 5;

    auto issue = [&](int k0, int st) {
        const uint32_t sb = smem + st * PASTAGE;
        #pragma unroll
        for (int i = 0; i < 8; i++) {
            int cidx = t + i * 128;
            int r = cidx >> 3, c8 = (cidx & 7) * 8;
            uint32_t so = (uint32_t)((r * PSTR + c8) * 2);
            size_t ga = (size_t)(m0 + r) * Dd + k0 + c8;
            CP16(sb + so, AH + ga);
            CP16(sb + PAX_B + so, AL + ga);
        }
        #pragma unroll
        for (int i = 0; i < 4; i++) {
            int cidx = t + i * 128;
            int r = cidx >> 3, c8 = (cidx & 7) * 8;
            uint32_t so = (uint32_t)((r * PSTR + c8) * 2);
            size_t gw = (size_t)(n0 + r) * Dd + k0 + c8;
            CP16(sb + 2 * PAX_B + so, WHg + gw);
            CP16(sb + 2 * PAX_B + PAW_B + so, WLg + gw);
        }
        CP_COMMIT();
    };

    #pragma unroll
    for (int rs = 0; rs < 2; rs++)
        #pragma unroll
        for (int j = 0; j < 8; j++)
            acc[rs][j][0] = acc[rs][j][1] = acc[rs][j][2] = acc[rs][j][3] = 0.0f;

    issue(0, 0);
    #pragma unroll
    for (int ks = 0; ks < 8; ks++) {
        const int cur = ks & 1;
        if (ks < 7) { issue((ks + 1) * 64, cur ^ 1); CP_WAIT(1); }
        else        { CP_WAIT(0); }
        __syncthreads();

        const uint32_t XHb = smem + cur * PASTAGE;
        const uint32_t XLb = XHb + PAX_B;
        const uint32_t WHb = XHb + 2 * PAX_B;
        const uint32_t WLb = WHb + PAW_B;

        uint32_t ah[2][4][4], al[2][4][4];
        #pragma unroll
        for (int rs = 0; rs < 2; rs++)
            #pragma unroll
            for (int c = 0; c < 4; c++) {
                uint32_t off = (uint32_t)(((32 * w + 16 * rs + (lane & 15)) * PSTR
                                           + c * 16 + (lane >> 4) * 8) * 2);
                ldsm4(ah[rs][c], XHb + off);
                ldsm4(al[rs][c], XLb + off);
            }
        #pragma unroll
        for (int j = 0; j < 8; j++) {
            uint32_t rowoff = (uint32_t)((8 * j + (lane & 7)) * (PSTR * 2));
            uint32_t koff   = (uint32_t)(((lane >> 3) * 8) * 2);
            uint32_t bh8[8], bl8[8];
            ldsm4(bh8,     WHb + rowoff + koff);
            ldsm4(bh8 + 4, WHb + rowoff + koff + 64);
            ldsm4(bl8,     WLb + rowoff + koff);
            ldsm4(bl8 + 4, WLb + rowoff + koff + 64);
            #pragma unroll
            for (int rs = 0; rs < 2; rs++)
                #pragma unroll
                for (int c = 0; c < 4; c++) {
                    mma16816(acc[rs][j], ah[rs][c], &bh8[2 * c]);
                    mma16816(acc[rs][j], ah[rs][c], &bl8[2 * c]);
                    mma16816(acc[rs][j], al[rs][c], &bh8[2 * c]);
                }
        }
        __syncthreads();
    }
}

// ===========================================================================
// Projection core B (R16): C[64x64], 4 warps, 16 rows/warp — used by oproj.
// ===========================================================================
#define PBX_B   (64 * PSTR * 2)
#define PBW_B   (64 * PSTR * 2)
#define PBSTAGE (2 * PBX_B + 2 * PBW_B)
#define PROJB_SMEM (2 * PBSTAGE)

__device__ __forceinline__ void proj_core_B(
    const __nv_bfloat16* __restrict__ AH, const __nv_bfloat16* __restrict__ AL,
    const __nv_bfloat16* __restrict__ WHg, const __nv_bfloat16* __restrict__ WLg,
    int m0, int n0, float acc[8][4], char* smc)
{
    const uint32_t smem = smem_u32(smc);
    const int t = threadIdx.x, lane = t & 31, w = t >> 5;

    auto issue = [&](int k0, int st) {
        const uint32_t sb = smem + st * PBSTAGE;
        #pragma unroll
        for (int i = 0; i < 4; i++) {
            int cidx = t + i * 128;
            int r = cidx >> 3, c8 = (cidx & 7) * 8;
            uint32_t so = (uint32_t)((r * PSTR + c8) * 2);
            size_t ga = (size_t)(m0 + r) * Dd + k0 + c8;
            size_t gw = (size_t)(n0 + r) * Dd + k0 + c8;
            CP16(sb + so, AH + ga);
            CP16(sb + PBX_B + so, AL + ga);
            CP16(sb + 2 * PBX_B + so, WHg + gw);
            CP16(sb + 2 * PBX_B + PBW_B + so, WLg + gw);
        }
        CP_COMMIT();
    };

    #pragma unroll
    for (int j = 0; j < 8; j++)
        acc[j][0] = acc[j][1] = acc[j][2] = acc[j][3] = 0.0f;

    issue(0, 0);
    #pragma unroll
    for (int ks = 0; ks < 8; ks++) {
        const int cur = ks & 1;
        if (ks < 7) { issue((ks + 1) * 64, cur ^ 1); CP_WAIT(1); }
        else        { CP_WAIT(0); }
        __syncthreads();

        const uint32_t XHb = smem + cur * PBSTAGE;
        const uint32_t XLb = XHb + PBX_B;
        const uint32_t WHb = XHb + 2 * PBX_B;
        const uint32_t WLb = WHb + PBW_B;

        uint32_t ah[4][4], al[4][4];
        #pragma unroll
        for (int c = 0; c < 4; c++) {
            uint32_t off = (uint32_t)(((16 * w + (lane & 15)) * PSTR
                                       + c * 16 + (lane >> 4) * 8) * 2);
            ldsm4(ah[c], XHb + off);
            ldsm4(al[c], XLb + off);
        }
        #pragma unroll
        for (int j = 0; j < 8; j++) {
            uint32_t rowoff = (uint32_t)((8 * j + (lane & 7)) * (PSTR * 2));
            uint32_t koff   = (uint32_t)(((lane >> 3) * 8) * 2);
            uint32_t bh8[8], bl8[8];
            ldsm4(bh8,     WHb + rowoff + koff);
            ldsm4(bh8 + 4, WHb + rowoff + koff + 64);
            ldsm4(bl8,     WLb + rowoff + koff);
            ldsm4(bl8 + 4, WLb + rowoff + koff + 64);
            #pragma unroll
            for (int c = 0; c < 4; c++) {
                mma16816(acc[j], ah[c], &bh8[2 * c]);
                mma16816(acc[j], ah[c], &bl8[2 * c]);
                mma16816(acc[j], al[c], &bh8[2 * c]);
            }
        }
        __syncthreads();
    }
}

// ---------------- Kernel 1: QKV projection + LayerNorm (core A) -----------
__global__ __launch_bounds__(128, 2) void qkv_mma_kernel(
    const float* __restrict__ bq, const float* __restrict__ bk,
    const float* __restrict__ bv,
    const float* __restrict__ qg, const float* __restrict__ qb,
    const float* __restrict__ kg, const float* __restrict__ kb)
{
    extern __shared__ char smc[];
    const int t = threadIdx.x, lane = t & 31, w = t >> 5;
    const int g = lane >> 2, tig = lane & 3;
    const int bx = blockIdx.x, by = blockIdx.y, z = blockIdx.z;

    const float* bvec;
    __nv_bfloat16 *outH, *outL;
    const float* gamma = nullptr; const float* beta = nullptr;
    if (z == 0)      { bvec = bq; outH = g_QhH; outL = g_QhL; gamma = qg; beta = qb; }
    else if (z == 1) { bvec = bk; outH = g_KhH; outL = g_KhL; gamma = kg; beta = kb; }
    else             { bvec = bv; outH = g_VhH; outL = g_VhL; }

    const int m0 = by * 128, n0 = bx * 64;
    float acc[2][8][4];
    proj_core_A(g_xH, g_xL, g_WH + (size_t)z * Dd * Dd,
                g_WL + (size_t)z * Dd * Dd, m0, n0, acc, smc);

    #pragma unroll
    for (int rs = 0; rs < 2; rs++)
        #pragma unroll
        for (int j = 0; j < 8; j++) {
            float2 bb = *(const float2*)(bvec + n0 + 8 * j + 2 * tig);
            acc[rs][j][0] += bb.x; acc[rs][j][1] += bb.y;
            acc[rs][j][2] += bb.x; acc[rs][j][3] += bb.y;
        }

    if (z < 2) {
        const float sc = (z == 0) ? 0.125f : 1.0f;
        #pragma unroll
        for (int rs = 0; rs < 2; rs++) {
            float s1A = 0, s2A = 0, s1B = 0, s2B = 0;
            #pragma unroll
            for (int j = 0; j < 8; j++) {
                s1A += acc[rs][j][0] + acc[rs][j][1];
                s2A += acc[rs][j][0] * acc[rs][j][0] + acc[rs][j][1] * acc[rs][j][1];
                s1B += acc[rs][j][2] + acc[rs][j][3];
                s2B += acc[rs][j][2] * acc[rs][j][2] + acc[rs][j][3] * acc[rs][j][3];
            }
            #pragma unroll
            for (int off = 1; off <= 2; off <<= 1) {
                s1A += __shfl_xor_sync(0xffffffffu, s1A, off);
                s2A += __shfl_xor_sync(0xffffffffu, s2A, off);
                s1B += __shfl_xor_sync(0xffffffffu, s1B, off);
                s2B += __shfl_xor_sync(0xffffffffu, s2B, off);
            }
            float mA = s1A * (1.0f / 64.0f), mB = s1B * (1.0f / 64.0f);
            float rA = rsqrtf(s2A * (1.0f / 64.0f) - mA * mA + 1e-6f);
            float rB = rsqrtf(s2B * (1.0f / 64.0f) - mB * mB + 1e-6f);
            #pragma unroll
            for (int j = 0; j < 8; j++) {
                int dh = 8 * j + 2 * tig;
                float2 gg = *(const float2*)(gamma + dh);
                float2 be = *(const float2*)(beta + dh);
                gg.x *= sc; gg.y *= sc; be.x *= sc; be.y *= sc;
                acc[rs][j][0] = (acc[rs][j][0] - mA) * rA * gg.x + be.x;
                acc[rs][j][1] = (acc[rs][j][1] - mA) * rA * gg.y + be.y;
                acc[rs][j][2] = (acc[rs][j][2] - mB) * rB * gg.x + be.x;
                acc[rs][j][3] = (acc[rs][j][3] - mB) * rB * gg.y + be.y;
            }
        }
    }

    #pragma unroll
    for (int rs = 0; rs < 2; rs++) {
        const int row1 = 32 * w + 16 * rs + g;
        const int m = m0 + row1, b = m >> 11, n = m & (Nn - 1);
        const size_t base = (((size_t)b * Hh + bx) * Nn + n) * DHd + 2 * tig;
        #pragma unroll
        for (int j = 0; j < 8; j++) {
            uint32_t hA, lA, hB, lB;
            split2(acc[rs][j][0], acc[rs][j][1], hA, lA);
            split2(acc[rs][j][2], acc[rs][j][3], hB, lB);
            *(uint32_t*)(outH + base + 8 * j)           = hA;
            *(uint32_t*)(outL + base + 8 * j)           = lA;
            *(uint32_t*)(outH + base + 8 * DHd + 8 * j) = hB;
            *(uint32_t*)(outL + base + 8 * DHd + 8 * j) = lB;
        }
    }
}

// ---------------- Kernel 2: flash attention (R14, best known) --------------
#define KVSTR 72
#define TILE_B (64 * KVSTR * 2)
#define OFF_KH 0
#define OFF_KL TILE_B
#define OFF_VH (2 * TILE_B)
#define OFF_VL (3 * TILE_B)
#define OFF_BI (4 * TILE_B)
#define BSTR   68
#define BIAS_B (64 * BSTR * 4)
#define STAGE_B (4 * TILE_B + BIAS_B)
#define ATT_SMEM (2 * STAGE_B)

__global__ __launch_bounds__(128, 2) void attn_mma_kernel(const float* __restrict__ bias)
{
    extern __shared__ char smc[];
    const uint32_t smem = smem_u32(smc);

    const int t = threadIdx.x, lane = t & 31, w = t >> 5;
    const int g = lane >> 2, tig = lane & 3;
    const int qt = blockIdx.x, bh = blockIdx.y;
    const int b = bh >> 3, h = bh & 7, q0 = qt * 64;

    const __nv_bfloat16* QgH = g_QhH + ((size_t)bh * Nn + q0) * DHd;
    const __nv_bfloat16* QgL = g_QhL + ((size_t)bh * Nn + q0) * DHd;
    const __nv_bfloat16* KbH = g_KhH + (size_t)bh * Nn * DHd;
    const __nv_bfloat16* KbL = g_KhL + (size_t)bh * Nn * DHd;
    const __nv_bfloat16* VbH = g_VhH + (size_t)bh * Nn * DHd;
    const __nv_bfloat16* VbL = g_VhL + (size_t)bh * Nn * DHd;
    const float* biasq = bias + ((size_t)b * Nn + q0) * Nn;

    const int row1 = 16 * w + g;

    uint32_t qh[4][4], ql[4][4];
    #pragma unroll
    for (int c = 0; c < 4; c++) {
        const int k0 = 16 * c + 2 * tig;
        const size_t rA = (size_t)row1 * DHd, rB = (size_t)(row1 + 8) * DHd;
        qh[c][0] = *(const uint32_t*)(QgH + rA + k0);
        qh[c][1] = *(const uint32_t*)(QgH + rB + k0);
        qh[c][2] = *(const uint32_t*)(QgH + rA + k0 + 8);
        qh[c][3] = *(const uint32_t*)(QgH + rB + k0 + 8);
        ql[c][0] = *(const uint32_t*)(QgL + rA + k0);
        ql[c][1] = *(const uint32_t*)(QgL + rB + k0);
        ql[c][2] = *(const uint32_t*)(QgL + rA + k0 + 8);
        ql[c][3] = *(const uint32_t*)(QgL + rB + k0 + 8);
    }

    auto issue_stage = [&](int kt, int st) {
        const size_t toff = (size_t)kt * 64 * DHd;
        const uint32_t sb = smem + st * STAGE_B;
        #pragma unroll
        for (int i = 0; i < 4; i++) {
            int cidx = t + i * 128;
            int r = cidx >> 3, c8 = (cidx & 7) * 8;
            uint32_t so = (uint32_t)((r * KVSTR + c8) * 2);
            size_t go = toff + (size_t)r * DHd + c8;
            CP16(sb + OFF_KH + so, KbH + go);
            CP16(sb + OFF_KL + so, KbL + go);
            CP16(sb + OFF_VH + so, VbH + go);
            CP16(sb + OFF_VL + so, VbL + go);
        }
        #pragma unroll
        for (int i = 0; i < 8; i++) {
            int cidx = t + i * 128;
            int r = cidx >> 4, c4 = (cidx & 15) * 4;
            CP16(sb + OFF_BI + (uint32_t)((r * BSTR + c4) * 4),
                 biasq + (size_t)r * Nn + kt * 64 + c4);
        }
        CP_COMMIT();
    };

    float o[8][4];
    #pragma unroll
    for (int j = 0; j < 8; j++)
        #pragma unroll
        for (int k = 0; k < 4; k++) o[j][k] = 0.0f;
    float lA = 0.0f, lB = 0.0f;

    issue_stage(0, 0);

    for (int kt = 0; kt < Nn / 64; kt++) {
        const int cur = kt & 1;
        if (kt + 1 < Nn / 64) { issue_stage(kt + 1, cur ^ 1); CP_WAIT(1); }
        else                  { CP_WAIT(0); }
        __syncthreads();

        const uint32_t KHb = smem + cur * STAGE_B + OFF_KH;
        const uint32_t KLb = smem + cur * STAGE_B + OFF_KL;
        const uint32_t VHb = smem + cur * STAGE_B + OFF_VH;
        const uint32_t VLb = smem + cur * STAGE_B + OFF_VL;
        const float* bs = (const float*)(smc + cur * STAGE_B + OFF_BI);

        const float* bArow = bs + row1 * BSTR + 2 * tig;
        const float* bBrow = bArow + 8 * BSTR;
        float2 vA[8], vB[8];
        #pragma unroll
        for (int j = 0; j < 8; j++) {
            vA[j] = *(const float2*)(bArow + 8 * j);
            vB[j] = *(const float2*)(bBrow + 8 * j);
        }

        float s[8][4];
        #pragma unroll
        for (int j = 0; j < 8; j++) {
            s[j][0] = s[j][1] = s[j][2] = s[j][3] = 0.0f;
            const uint32_t rowoff = (uint32_t)((8 * j + (lane & 7)) * (KVSTR * 2));
            const uint32_t koff   = (uint32_t)(((lane >> 3) * 8) * 2);
            uint32_t bhf[8], blf[8];
            ldsm4(bhf,     KHb + rowoff + koff);
            ldsm4(bhf + 4, KHb + rowoff + koff + 64);
            ldsm4(blf,     KLb + rowoff + koff);
            ldsm4(blf + 4, KLb + rowoff + koff + 64);
            #pragma unroll
            for (int c = 0; c < 4; c++) {
                mma16816(s[j], qh[c], &bhf[2 * c]);
                mma16816(s[j], qh[c], &blf[2 * c]);
                mma16816(s[j], ql[c], &bhf[2 * c]);
            }
        }

        #pragma unroll
        for (int j = 0; j < 8; j++) {
            s[j][0] = expm16(s[j][0] + vA[j].x);
            s[j][1] = expm16(s[j][1] + vA[j].y);
            s[j][2] = expm16(s[j][2] + vB[j].x);
            s[j][3] = expm16(s[j][3] + vB[j].y);
            lA += s[j][0] + s[j][1];
            lB += s[j][2] + s[j][3];
        }

        uint32_t ph[4][4], pl[4][4];
        #pragma unroll
        for (int c = 0; c < 4; c++) {
            split2(s[2*c][0],   s[2*c][1],   ph[c][0], pl[c][0]);
            split2(s[2*c][2],   s[2*c][3],   ph[c][1], pl[c][1]);
            split2(s[2*c+1][0], s[2*c+1][1], ph[c][2], pl[c][2]);
            split2(s[2*c+1][2], s[2*c+1][3], ph[c][3], pl[c][3]);
        }

        #pragma unroll
        for (int j = 0; j < 8; j++) {
            const uint32_t rowoff = (uint32_t)((((lane >> 3) * 8) + (lane & 7)) * (KVSTR * 2));
            const uint32_t coff   = (uint32_t)(8 * j * 2);
            uint32_t vhf[8], vlf[8];
            ldsm4t(vhf,     VHb + rowoff + coff);
            ldsm4t(vhf + 4, VHb + rowoff + coff + 32 * (KVSTR * 2));
            ldsm4t(vlf,     VLb + rowoff + coff);
            ldsm4t(vlf + 4, VLb + rowoff + coff + 32 * (KVSTR * 2));
            #pragma unroll
            for (int c = 0; c < 4; c++) {
                mma16816(o[j], ph[c], &vhf[2 * c]);
                mma16816(o[j], ph[c], &vlf[2 * c]);
                mma16816(o[j], pl[c], &vhf[2 * c]);
            }
        }
        __syncthreads();
    }

    lA += __shfl_xor_sync(0xffffffffu, lA, 1);
    lA += __shfl_xor_sync(0xffffffffu, lA, 2);
    lB += __shfl_xor_sync(0xffffffffu, lB, 1);
    lB += __shfl_xor_sync(0xffffffffu, lB, 2);

    const float rlA = 1.0f / lA, rlB = 1.0f / lB;
    const size_t cbase = ((size_t)b * Nn + q0 + row1) * Dd + h * DHd + 2 * tig;
    #pragma unroll
    for (int j = 0; j < 8; j++) {
        uint32_t hA, lA_, hB, lB_;
        split2(o[j][0] * rlA, o[j][1] * rlA, hA, lA_);
        split2(o[j][2] * rlB, o[j][3] * rlB, hB, lB_);
        *(uint32_t*)(g_ctxH + cbase + 8 * j)                  = hA;
        *(uint32_t*)(g_ctxL + cbase + 8 * j)                  = lA_;
        *(uint32_t*)(g_ctxH + cbase + 8 * (size_t)Dd + 8 * j) = hB;
        *(uint32_t*)(g_ctxL + cbase + 8 * (size_t)Dd + 8 * j) = lB_;
    }
}

// ---------------- Kernel 3: output projection (core B, 3 CTAs/SM) ----------
__global__ __launch_bounds__(128, 3) void oproj_mma_kernel(
    const float* __restrict__ bo, float* __restrict__ out)
{
    extern __shared__ char smc[];
    const int t = threadIdx.x, lane = t & 31, w = t >> 5;
    const int g = lane >> 2, tig = lane & 3;
    const int bx = blockIdx.x, by = blockIdx.y;

    const int m0 = by * 64, n0 = bx * 64;
    float acc[8][4];
    proj_core_B(g_ctxH, g_ctxL, g_WH + (size_t)3 * Dd * Dd,
                g_WL + (size_t)3 * Dd * Dd, m0, n0, acc, smc);

    const int row1 = 16 * w + g;
    const int m = m0 + row1;
    float* oA = out + (size_t)m * Dd + n0 + 2 * tig;
    float* oB = oA + 8 * (size_t)Dd;
    #pragma unroll
    for (int j = 0; j < 8; j++) {
        float2 bb = *(const float2*)(bo + n0 + 8 * j + 2 * tig);
        *(float2*)(oA + 8 * j) = make_float2(acc[j][0] + bb.x, acc[j][1] + bb.y);
        *(float2*)(oB + 8 * j) = make_float2(acc[j][2] + bb.x, acc[j][3] + bb.y);
    }
}

// ---------------------------------------------------------------------------
extern "C" void kernel_launch(void* const* d_in, const int* in_sizes, int n_in,
                              void* d_out, int out_size)
{
    (void)in_sizes; (void)n_in; (void)out_size;
    const float* x    = (const float*)d_in[0];
    const float* bias = (const float*)d_in[1];
    const float* Wq   = (const float*)d_in[2];
    const float* bq   = (const float*)d_in[3];
    const float* Wk   = (const float*)d_in[4];
    const float* bk   = (const float*)d_in[5];
    const float* Wv   = (const float*)d_in[6];
    const float* bv   = (const float*)d_in[7];
    const float* Wo   = (const float*)d_in[8];
    const float* bo   = (const float*)d_in[9];
    const float* qg   = (const float*)d_in[10];
    const float* qb   = (const float*)d_in[11];
    const float* kg   = (const float*)d_in[12];
    const float* kb   = (const float*)d_in[13];
    float* out = (float*)d_out;

    cudaFuncSetAttribute(qkv_mma_kernel,
                         cudaFuncAttributeMaxDynamicSharedMemorySize, PROJA_SMEM);
    cudaFuncSetAttribute(oproj_mma_kernel,
                         cudaFuncAttributeMaxDynamicSharedMemorySize, PROJB_SMEM);
    cudaFuncSetAttribute(oproj_mma_kernel,
                         cudaFuncAttributePreferredSharedMemoryCarveout, 100);
    cudaFuncSetAttribute(attn_mma_kernel,
                         cudaFuncAttributeMaxDynamicSharedMemorySize, ATT_SMEM);

    presplit_kernel<<<(unsigned)((NX4 + 4 * NW4) / 256), 256>>>(x, Wq, Wk, Wv, Wo);
    qkv_mma_kernel<<<dim3(Dd / 64, (Bb * Nn) / 128, 3), 128, PROJA_SMEM>>>(
        bq, bk, bv, qg, qb, kg, kb);
    attn_mma_kernel<<<dim3(Nn / 64, Bb * Hh), 128, ATT_SMEM>>>(bias);
    oproj_mma_kernel<<<dim3(Dd / 64, (Bb * Nn) / 64), 128, PROJB_SMEM>>>(bo, out);
}